// round 6
// baseline (speedup 1.0000x reference)
#include <cuda_runtime.h>

#define BB   4
#define CIN  64
#define COUT 64
#define NPTS 8192
#define KNN  16
#define NQ   (BB * NPTS)
#define CAP  192            // per-query buffer (two halves of HCAP)
#define HCAP 96
#define SAMP 1024
#define HALF 4096           // candidates per collect half
#define TCB  1024           // candidates per staged tile

// Static scratch (no runtime allocation allowed)
__device__ int                g_idx[NQ * KNN];          // [q][k]
__device__ float              g_z[NQ * COUT];           // zT[b][n][o]
__device__ float              g_thr[NQ];                // per-query threshold
__device__ unsigned long long g_buf[(size_t)NQ * CAP];  // hits: (j<<32)|d
__device__ int                g_cnt[NQ * 2];            // true hit count per half
__device__ int                g_wcount;                 // fallback worklist size
__device__ int                g_wlist[NQ];

// --------------------------- f32x2 helpers ---------------------------------
__device__ __forceinline__ unsigned long long pk2(float lo, float hi) {
    unsigned long long r;
    asm("mov.b64 %0, {%1, %2};" : "=l"(r) : "f"(lo), "f"(hi));
    return r;
}
__device__ __forceinline__ void upk2(unsigned long long v, float& lo, float& hi) {
    asm("mov.b64 {%0, %1}, %2;" : "=f"(lo), "=f"(hi) : "l"(v));
}
__device__ __forceinline__ unsigned long long mul2(unsigned long long a, unsigned long long b) {
    unsigned long long r;
    asm("mul.rn.f32x2 %0, %1, %2;" : "=l"(r) : "l"(a), "l"(b));
    return r;
}
__device__ __forceinline__ unsigned long long add2(unsigned long long a, unsigned long long b) {
    unsigned long long r;
    asm("add.rn.f32x2 %0, %1, %2;" : "=l"(r) : "l"(a), "l"(b));
    return r;
}
__device__ __forceinline__ unsigned long long fma2(unsigned long long a, unsigned long long b,
                                                   unsigned long long c) {
    unsigned long long r;
    asm("fma.rn.f32x2 %0, %1, %2, %3;" : "=l"(r) : "l"(a), "l"(b), "l"(c));
    return r;
}

// ---------------------------------------------------------------------------
// Threshold: 8th smallest distance over a stride-8 1024-point subsample.
// ---------------------------------------------------------------------------
__global__ void __launch_bounds__(128) knn_thresh(const float* __restrict__ coords) {
    __shared__ float4 sp[SAMP];
    int tid = threadIdx.x;
    int b   = blockIdx.x >> 6;                  // 64 blocks per batch
    const float* cb = coords + b * 3 * NPTS;

    for (int t = tid; t < SAMP; t += 128) {
        int j = t * 8;
        float cx = cb[j], cy = cb[NPTS + j], cz = cb[2 * NPTS + j];
        sp[t] = make_float4(cx, cy, cz, (cx * cx + cy * cy) + cz * cz);
    }
    __syncthreads();

    int q = blockIdx.x * 128 + tid;
    int n = q & (NPTS - 1);
    float qx = cb[n], qy = cb[NPTS + n], qz = cb[2 * NPTS + n];
    float sqi = (qx * qx + qy * qy) + qz * qz;

    float t8[8];
#pragma unroll
    for (int s = 0; s < 8; s++) t8[s] = __int_as_float(0x7f800000);

#pragma unroll 4
    for (int t = 0; t < SAMP; t++) {
        float4 c = sp[t];
        float inner = fmaf(qz, c.z, fmaf(qy, c.y, qx * c.x));
        float d = fmaf(-2.0f, inner, sqi + c.w);
        if (d < t8[7]) {
            float v = d;
#pragma unroll
            for (int s = 0; s < 8; s++) {
                float lo = fminf(t8[s], v);
                float hi = fmaxf(t8[s], v);
                t8[s] = lo; v = hi;
            }
        }
    }
    g_thr[q] = t8[7];
}

// ---------------------------------------------------------------------------
// Collect (split): each block scans HALF=4096 candidates for its 128 queries,
// appending hits d<=T to its half of the per-query global buffer. Ascending j
// within each half. True (unclamped) count recorded for overflow detection.
// ---------------------------------------------------------------------------
__global__ void __launch_bounds__(128) knn_collect(const float* __restrict__ coords) {
    __shared__ float4 sxy[TCB / 2];   // (x0,x1,y0,y1) per pair
    __shared__ float4 szw[TCB / 2];   // (z0,z1,sq0,sq1) per pair

    int tid    = threadIdx.x;
    int half   = blockIdx.x >> 8;             // 0 or 1
    int qblock = blockIdx.x & 255;
    int q      = qblock * 128 + tid;
    int b      = qblock >> 6;
    int n      = q & (NPTS - 1);
    const float* cb = coords + b * 3 * NPTS;

    float qx = cb[n], qy = cb[NPTS + n], qz = cb[2 * NPTS + n];
    float sqi = (qx * qx + qy * qy) + qz * qz;

    unsigned long long qx2 = pk2(qx, qx), qy2 = pk2(qy, qy), qz2 = pk2(qz, qz);
    unsigned long long sq2 = pk2(sqi, sqi);
    unsigned long long m2  = pk2(-2.0f, -2.0f);

    float T = g_thr[q];
    int cnt = 0;
    unsigned long long* bp = g_buf + (size_t)q * CAP + half * HCAP;

    int c0 = half * HALF;
    for (int tb = c0; tb < c0 + HALF; tb += TCB) {
        __syncthreads();
        float* fxy = (float*)sxy;
        float* fzw = (float*)szw;
        for (int e = tid; e < TCB; e += 128) {
            int j = tb + e;
            float cx = cb[j], cy = cb[NPTS + j], cz = cb[2 * NPTS + j];
            int p = e >> 1, o = e & 1;
            fxy[p * 4 + o]     = cx;
            fxy[p * 4 + 2 + o] = cy;
            fzw[p * 4 + o]     = cz;
            fzw[p * 4 + 2 + o] = (cx * cx + cy * cy) + cz * cz;
        }
        __syncthreads();

#pragma unroll 8
        for (int p = 0; p < TCB / 2; p++) {
            float4 a  = sxy[p];
            float4 zz = szw[p];
            unsigned long long x01 = pk2(a.x, a.y),  y01 = pk2(a.z, a.w);
            unsigned long long z01 = pk2(zz.x, zz.y), w01 = pk2(zz.z, zz.w);
            unsigned long long t0 = mul2(qx2, x01);
            t0 = fma2(qy2, y01, t0);
            t0 = fma2(qz2, z01, t0);
            unsigned long long d2 = fma2(m2, t0, add2(sq2, w01));
            float d0, d1;
            upk2(d2, d0, d1);
            if (fminf(d0, d1) <= T) {
                int j0 = tb + 2 * p;
                if (d0 <= T) {
                    if (cnt < HCAP)
                        bp[cnt] = ((unsigned long long)(unsigned)j0 << 32) | __float_as_uint(d0);
                    cnt++;
                }
                if (d1 <= T) {
                    if (cnt < HCAP)
                        bp[cnt] = ((unsigned long long)(unsigned)(j0 + 1) << 32) | __float_as_uint(d1);
                    cnt++;
                }
            }
        }
    }
    g_cnt[q * 2 + half] = cnt;
}

// ---------------------------------------------------------------------------
// Select: exact top-16 bubble over the two half-buffers (half0 then half1 =
// ascending j overall -> stable top_k tie-break). Flags rare bad queries.
// ---------------------------------------------------------------------------
__global__ void __launch_bounds__(128) knn_select() {
    int q = blockIdx.x * 128 + threadIdx.x;
    int c0 = g_cnt[q * 2 + 0];
    int c1 = g_cnt[q * 2 + 1];

    float ds[KNN];
    int   is_[KNN];
#pragma unroll
    for (int s = 0; s < KNN; s++) { ds[s] = __int_as_float(0x7f800000); is_[s] = 0; }

    const unsigned long long* bp = g_buf + (size_t)q * CAP;
#pragma unroll 1
    for (int h = 0; h < 2; h++) {
        int m = (h == 0 ? c0 : c1);
        if (m > HCAP) m = HCAP;
        const unsigned long long* hp = bp + h * HCAP;
        for (int t = 0; t < m; t++) {
            unsigned long long e = hp[t];
            float d = __uint_as_float((unsigned)e);
            int   j = (int)(e >> 32);
            if (d < ds[KNN - 1]) {
                float vd = d; int vi = j;
#pragma unroll
                for (int s = 0; s < KNN; s++) {
                    float od = ds[s]; int oi = is_[s];
                    bool  pr = vd < od;
                    ds[s]  = pr ? vd : od;
                    is_[s] = pr ? vi : oi;
                    vd     = pr ? od : vd;
                    vi     = pr ? oi : vi;
                }
            }
        }
    }

    int* op = g_idx + q * KNN;
#pragma unroll
    for (int s = 0; s < KNN; s++) op[s] = is_[s];

    if (c0 + c1 < KNN || c0 > HCAP || c1 > HCAP) {
        int slot = atomicAdd(&g_wcount, 1);
        g_wlist[slot] = q;
    }
}

// ---------------------------------------------------------------------------
// Fallback: worklist-driven warp-cooperative exact scan (proven in R4/R5).
// ---------------------------------------------------------------------------
__global__ void __launch_bounds__(32) knn_fallback(const float* __restrict__ coords) {
    int lane = threadIdx.x;
    int nw = g_wcount;

    for (int w = blockIdx.x; w < nw; w += 256) {
        int q = g_wlist[w];
        int b = q >> 13, n = q & (NPTS - 1);
        const float* cb = coords + b * 3 * NPTS;
        float qx = cb[n], qy = cb[NPTS + n], qz = cb[2 * NPTS + n];
        float sqi = (qx * qx + qy * qy) + qz * qz;

        float ds[KNN];
        int   is_[KNN];
#pragma unroll
        for (int s = 0; s < KNN; s++) { ds[s] = __int_as_float(0x7f800000); is_[s] = 0x7fffffff; }

        for (int i = 0; i < NPTS / 32; i++) {
            int j = i * 32 + lane;
            float cx = cb[j], cy = cb[NPTS + j], cz = cb[2 * NPTS + j];
            float sq = (cx * cx + cy * cy) + cz * cz;
            float inner = fmaf(qz, cz, fmaf(qy, cy, qx * cx));
            float d = fmaf(-2.0f, inner, sqi + sq);
            if (d < ds[KNN - 1]) {
                float vd = d; int vi = j;
#pragma unroll
                for (int s = 0; s < KNN; s++) {
                    float od = ds[s]; int oi = is_[s];
                    bool  pr = vd < od;
                    ds[s]  = pr ? vd : od;
                    is_[s] = pr ? vi : oi;
                    vd     = pr ? od : vd;
                    vi     = pr ? oi : vi;
                }
            }
        }

        __shared__ float sd[32][KNN];
        __shared__ int   sj[32][KNN];
#pragma unroll
        for (int s = 0; s < KNN; s++) { sd[lane][s] = ds[s]; sj[lane][s] = is_[s]; }
        __syncwarp();

        int ptr = 0;
        for (int k = 0; k < KNN; k++) {
            float cd = (ptr < KNN) ? sd[lane][ptr] : __int_as_float(0x7f800000);
            int   cj = (ptr < KNN) ? sj[lane][ptr] : 0x7fffffff;
            float wd = cd; int wj = cj;
#pragma unroll
            for (int off = 16; off > 0; off >>= 1) {
                float od = __shfl_xor_sync(0xffffffffu, wd, off);
                int   oj = __shfl_xor_sync(0xffffffffu, wj, off);
                if (od < wd || (od == wd && oj < wj)) { wd = od; wj = oj; }
            }
            if (wd == cd && wj == cj) ptr++;
            if (lane == 0) g_idx[q * KNN + k] = wj;
        }
        __syncwarp();
    }
}

// ---------------------------------------------------------------------------
// GEMM: z[b][n][o] = sum_c W[o][c] * x[b][c][n]; zeroes worklist counter.
// ---------------------------------------------------------------------------
__global__ void __launch_bounds__(128) gemm_kernel(const float* __restrict__ x,
                                                   const float* __restrict__ W) {
    if (blockIdx.x == 0 && threadIdx.x == 0) g_wcount = 0;

    __shared__ float ws[COUT * CIN];
    int tid = threadIdx.x;
#pragma unroll
    for (int u = 0; u < 8; u++)
        ((float4*)ws)[tid + u * 128] = ((const float4*)W)[tid + u * 128];
    __syncthreads();

    int b     = blockIdx.x >> 7;
    int ntile = (blockIdx.x & 127) * 64;
    int nl    = tid & 63;
    int o0    = (tid >> 6) * 32;
    int n     = ntile + nl;

    const float* xb = x + b * CIN * NPTS;

    float acc[32];
#pragma unroll
    for (int i = 0; i < 32; i++) acc[i] = 0.0f;

    for (int c = 0; c < CIN; c += 4) {
        float xv0 = xb[(c + 0) * NPTS + n];
        float xv1 = xb[(c + 1) * NPTS + n];
        float xv2 = xb[(c + 2) * NPTS + n];
        float xv3 = xb[(c + 3) * NPTS + n];
#pragma unroll
        for (int i = 0; i < 32; i++) {
            float4 w4 = *(const float4*)&ws[(o0 + i) * CIN + c];
            acc[i] = fmaf(w4.x, xv0, acc[i]);
            acc[i] = fmaf(w4.y, xv1, acc[i]);
            acc[i] = fmaf(w4.z, xv2, acc[i]);
            acc[i] = fmaf(w4.w, xv3, acc[i]);
        }
    }

    float* zp = g_z + ((size_t)b * NPTS + n) * COUT + o0;
#pragma unroll
    for (int i = 0; i < 32; i += 4)
        *(float4*)&zp[i] = make_float4(acc[i], acc[i + 1], acc[i + 2], acc[i + 3]);
}

// ---------------------------------------------------------------------------
// Max-gather + coords passthrough (tail blocks).
// ---------------------------------------------------------------------------
#define MG_BLOCKS   (BB * 256)
#define CP_FLOAT4   (BB * 3 * NPTS / 4)
#define CP_BLOCKS   (CP_FLOAT4 / 256)

__global__ void __launch_bounds__(256) maxgather_kernel(float* __restrict__ y,
                                                        const float* __restrict__ coords) {
    if (blockIdx.x >= MG_BLOCKS) {
        int i = (blockIdx.x - MG_BLOCKS) * 256 + threadIdx.x;
        float4* dst = (float4*)(y + (size_t)BB * COUT * NPTS);
        dst[i] = ((const float4*)coords)[i];
        return;
    }

    __shared__ float yt[COUT][33];

    int tid = threadIdx.x;
    int w   = tid >> 5;
    int l   = tid & 31;
    int b     = blockIdx.x >> 8;
    int ntile = (blockIdx.x & 255) * 32;

    const float* zb = g_z + (size_t)b * NPTS * COUT;
    const float NEG_INF = __int_as_float(0xff800000);

    for (int qq = 0; qq < 4; qq++) {
        int nl = w * 4 + qq;
        int n  = ntile + nl;
        const int* ip = g_idx + ((size_t)b * NPTS + n) * KNN;
        float m0 = NEG_INF, m1 = NEG_INF;
#pragma unroll
        for (int k = 0; k < KNN; k++) {
            int r = __ldg(&ip[k]);
            const float* zr = zb + (size_t)r * COUT;
            m0 = fmaxf(m0, zr[l]);
            m1 = fmaxf(m1, zr[l + 32]);
        }
        yt[l][nl]      = m0;
        yt[l + 32][nl] = m1;
    }
    __syncthreads();

#pragma unroll
    for (int e = tid; e < COUT * 32; e += 256) {
        int o  = e >> 5;
        int nl = e & 31;
        y[((size_t)b * COUT + o) * NPTS + ntile + nl] = yt[o][nl];
    }
}

// ---------------------------------------------------------------------------
extern "C" void kernel_launch(void* const* d_in, const int* in_sizes, int n_in,
                              void* d_out, int out_size) {
    const float* x      = (const float*)d_in[0];
    const float* coords = (const float*)d_in[1];
    const float* W      = (const float*)d_in[2];
    float*       out    = (float*)d_out;

    gemm_kernel<<<BB * 128, 128>>>(x, W);
    knn_thresh<<<NQ / 128, 128>>>(coords);
    knn_collect<<<2 * (NQ / 128), 128>>>(coords);
    knn_select<<<NQ / 128, 128>>>();
    knn_fallback<<<256, 32>>>(coords);
    maxgather_kernel<<<MG_BLOCKS + CP_BLOCKS, 256>>>(out, coords);
}